// round 5
// baseline (speedup 1.0000x reference)
#include <cuda_runtime.h>
#include <cstdint>

// Problem constants
#define NB     4
#define KWIN   2048
#define DMODEL 512
#define NHEAD  8
#define HDIM   64

// Scratch (allocation-free rule: __device__ globals).
// Layout for all four: [B, K, H*64] row-major == [8192, 512]
__device__ float g_qp[NB * KWIN * DMODEL];
__device__ float g_kp[NB * KWIN * DMODEL];
__device__ float g_vp[NB * KWIN * DMODEL];
__device__ float g_ct[NB * KWIN * DMODEL];

// ---------------------------------------------------------------------------
// Generic SGEMM: C[m, nb*64 + n] = X[m, :] (512) @ Wt[:, n] + bias
//   grid = (8192/128, 8), block = 128
//   Wt = W + blockIdx.y * wstride_y, element (k, n) at Wt[k*ldb + n]
//   Used for:
//     projections: wstride_y = 512*64, ldb = 64   (per-head weight block)
//     output proj: wstride_y = 64,     ldb = 512  (column slice of W_o)
//   xsel==1 -> read X from g_ct; osel selects g_qp/g_kp/g_vp or `out`.
// ---------------------------------------------------------------------------
__global__ __launch_bounds__(128)
void gemm512_kernel(const float* X, const float* __restrict__ W,
                    const float* __restrict__ bias, float* out,
                    int wstride_y, int ldb, int xsel, int osel)
{
    const float* Xp = (xsel == 1) ? (const float*)g_ct : X;
    float* op = out;
    if (osel == 1) op = g_qp;
    else if (osel == 2) op = g_kp;
    else if (osel == 3) op = g_vp;

    __shared__ float As[16][128];   // [k][m] transposed
    __shared__ float Bs[16][64];    // [k][n]

    const int tid = threadIdx.x;
    const int txc = tid & 7;        // col group: cols txc*8..+7
    const int tyr = tid >> 3;       // row group: rows tyr*8..+7
    const int m0  = blockIdx.x * 128;
    const int nb  = blockIdx.y;
    const float* Wt = W + (size_t)nb * wstride_y;

    float C[8][8];
#pragma unroll
    for (int i = 0; i < 8; ++i)
#pragma unroll
        for (int j = 0; j < 8; ++j) C[i][j] = 0.f;

    for (int k0 = 0; k0 < 512; k0 += 16) {
        // A tile: rows m0..m0+127, cols k0..k0+15 (coalesced, store transposed)
#pragma unroll
        for (int j = 0; j < 4; ++j) {
            int f   = tid + 128 * j;        // 0..511 float4 slots
            int row = f >> 2;               // 0..127
            int q4  = (f & 3) << 2;         // 0,4,8,12
            float4 v = *(const float4*)(Xp + (size_t)(m0 + row) * 512 + k0 + q4);
            As[q4 + 0][row] = v.x;
            As[q4 + 1][row] = v.y;
            As[q4 + 2][row] = v.z;
            As[q4 + 3][row] = v.w;
        }
        // B tile: rows k0..k0+15, 64 cols
#pragma unroll
        for (int j = 0; j < 2; ++j) {
            int f  = tid * 2 + j;           // 0..255 float4 slots
            int r  = f >> 4;                // 0..15
            int c4 = (f & 15) << 2;         // 0..60
            *(float4*)&Bs[r][c4] = *(const float4*)(Wt + (size_t)(k0 + r) * ldb + c4);
        }
        __syncthreads();

#pragma unroll
        for (int kk = 0; kk < 16; ++kk) {
            float a[8], b[8];
            *(float4*)&a[0] = *(const float4*)&As[kk][tyr * 8];
            *(float4*)&a[4] = *(const float4*)&As[kk][tyr * 8 + 4];
            *(float4*)&b[0] = *(const float4*)&Bs[kk][txc * 8];
            *(float4*)&b[4] = *(const float4*)&Bs[kk][txc * 8 + 4];
#pragma unroll
            for (int i = 0; i < 8; ++i)
#pragma unroll
                for (int j = 0; j < 8; ++j)
                    C[i][j] += a[i] * b[j];
        }
        __syncthreads();
    }

    float bb[8];
#pragma unroll
    for (int j = 0; j < 8; ++j) bb[j] = bias[nb * 64 + txc * 8 + j];

#pragma unroll
    for (int i = 0; i < 8; ++i) {
        float* o = op + (size_t)(m0 + tyr * 8 + i) * 512 + nb * 64 + txc * 8;
        float4 v0 = make_float4(C[i][0] + bb[0], C[i][1] + bb[1],
                                C[i][2] + bb[2], C[i][3] + bb[3]);
        float4 v1 = make_float4(C[i][4] + bb[4], C[i][5] + bb[5],
                                C[i][6] + bb[6], C[i][7] + bb[7]);
        *(float4*)o       = v0;
        *(float4*)(o + 4) = v1;
    }
}

// ---------------------------------------------------------------------------
// Causal flash attention, fp32.
//   grid = (32 q-tiles, B*H = 32), block = 256 (16x16, 4x4 microtile)
//   Per (b,h): Q,K,V planes are [2048, 64] with row stride 512 in g_qp/kp/vp.
//   Writes heads output into g_ct[b, k, h*64 + v] (same layout).
//   Smem: Qs[d][r], KPs = K-as-[d][c] then reused as P-as-[c][r], Vs[c][v].
//   3 * 16KB = 48KB static smem exactly.
// ---------------------------------------------------------------------------
__global__ __launch_bounds__(256)
void attn_kernel()
{
    __shared__ float Qs[64][64];    // [d][r]
    __shared__ float KPs[64][64];   // K: [d][c]; after S-GEMM reused as P: [c][r]
    __shared__ float Vs[64][64];    // [c][v]

    const int qi  = (int)gridDim.x - 1 - (int)blockIdx.x;  // big tiles first
    const int bh  = blockIdx.y;
    const int b   = bh >> 3;
    const int h   = bh & 7;
    const int tid = threadIdx.x;
    const int tx  = tid & 15;       // col group (4 cols)
    const int ty  = tid >> 4;       // row group (4 rows)
    const float scale   = 0.022097086912079608f;  // 1/sqrt(2048)
    const float NEG_INF = __int_as_float(0xff800000);

    const size_t plane = (size_t)b * (KWIN * DMODEL) + (size_t)h * 64;
    const float* qp = g_qp;
    const float* kp = g_kp;
    const float* vp = g_vp;

    // Load Q tile transposed: Qs[d][r], rows qi*64..+63
    {
        int r  = tid >> 2;
        int dq = (tid & 3) << 4;
        const float* src = qp + plane + (size_t)(qi * 64 + r) * 512 + dq;
#pragma unroll
        for (int j = 0; j < 4; ++j) {
            float4 v = *(const float4*)(src + j * 4);
            Qs[dq + j * 4 + 0][r] = v.x;
            Qs[dq + j * 4 + 1][r] = v.y;
            Qs[dq + j * 4 + 2][r] = v.z;
            Qs[dq + j * 4 + 3][r] = v.w;
        }
    }

    float O[4][4];
    float m_i[4], l_i[4];
#pragma unroll
    for (int i = 0; i < 4; ++i) {
        m_i[i] = NEG_INF;
        l_i[i] = 0.f;
#pragma unroll
        for (int j = 0; j < 4; ++j) O[i][j] = 0.f;
    }

    for (int kt = 0; kt <= qi; ++kt) {
        __syncthreads();   // prior chunk done reading KPs/Vs (and Qs store visible)
        {
            int c  = tid >> 2;
            int dq = (tid & 3) << 4;
            const float* ks = kp + plane + (size_t)(kt * 64 + c) * 512 + dq;
            const float* vs = vp + plane + (size_t)(kt * 64 + c) * 512 + dq;
#pragma unroll
            for (int j = 0; j < 4; ++j) {
                float4 v = *(const float4*)(ks + j * 4);
                KPs[dq + j * 4 + 0][c] = v.x;
                KPs[dq + j * 4 + 1][c] = v.y;
                KPs[dq + j * 4 + 2][c] = v.z;
                KPs[dq + j * 4 + 3][c] = v.w;
            }
#pragma unroll
            for (int j = 0; j < 4; ++j)
                *(float4*)&Vs[c][dq + j * 4] = *(const float4*)(vs + j * 4);
        }
        __syncthreads();

        // S = Q @ K^T (4x4 per thread), reduce over d
        float S[4][4];
#pragma unroll
        for (int i = 0; i < 4; ++i)
#pragma unroll
            for (int j = 0; j < 4; ++j) S[i][j] = 0.f;

#pragma unroll 8
        for (int d = 0; d < 64; ++d) {
            float a[4], kv[4];
            *(float4*)a  = *(const float4*)&Qs[d][ty * 4];
            *(float4*)kv = *(const float4*)&KPs[d][tx * 4];
#pragma unroll
            for (int i = 0; i < 4; ++i)
#pragma unroll
                for (int j = 0; j < 4; ++j)
                    S[i][j] += a[i] * kv[j];
        }

        // scale + causal mask + online softmax (row reduce over tx lanes)
        const bool diag = (kt == qi);
#pragma unroll
        for (int i = 0; i < 4; ++i) {
            const int rg = ty * 4 + i;
#pragma unroll
            for (int j = 0; j < 4; ++j) {
                float s = S[i][j] * scale;
                if (diag && (tx * 4 + j > rg)) s = NEG_INF;
                S[i][j] = s;
            }
            float mx = fmaxf(fmaxf(S[i][0], S[i][1]), fmaxf(S[i][2], S[i][3]));
#pragma unroll
            for (int off = 1; off < 16; off <<= 1)
                mx = fmaxf(mx, __shfl_xor_sync(0xffffffffu, mx, off));
            const float mn = fmaxf(m_i[i], mx);
            float sum = 0.f;
#pragma unroll
            for (int j = 0; j < 4; ++j) {
                float p = __expf(S[i][j] - mn);
                S[i][j] = p;
                sum += p;
            }
#pragma unroll
            for (int off = 1; off < 16; off <<= 1)
                sum += __shfl_xor_sync(0xffffffffu, sum, off);
            const float alpha = __expf(m_i[i] - mn);
            l_i[i] = l_i[i] * alpha + sum;
            m_i[i] = mn;
#pragma unroll
            for (int j = 0; j < 4; ++j) O[i][j] *= alpha;
        }

        __syncthreads();   // all threads done reading KPs as K
        // store P transposed: KPs[c][r]
#pragma unroll
        for (int j = 0; j < 4; ++j)
#pragma unroll
            for (int i = 0; i < 4; ++i)
                KPs[tx * 4 + j][ty * 4 + i] = S[i][j];
        __syncthreads();

        // O += P @ V, reduce over c
#pragma unroll 8
        for (int c = 0; c < 64; ++c) {
            float a[4], vv[4];
            *(float4*)a  = *(const float4*)&KPs[c][ty * 4];
            *(float4*)vv = *(const float4*)&Vs[c][tx * 4];
#pragma unroll
            for (int i = 0; i < 4; ++i)
#pragma unroll
                for (int j = 0; j < 4; ++j)
                    O[i][j] += a[i] * vv[j];
        }
    }

    // normalize + write heads output into concat layout [b, k, h*64 + v]
#pragma unroll
    for (int i = 0; i < 4; ++i) {
        const float inv = 1.f / l_i[i];
        float* o = g_ct + plane + (size_t)(qi * 64 + ty * 4 + i) * 512 + tx * 4;
        *(float4*)o = make_float4(O[i][0] * inv, O[i][1] * inv,
                                  O[i][2] * inv, O[i][3] * inv);
    }
}

// ---------------------------------------------------------------------------
// Launch: 3 projections -> attention -> output projection (one stream, serial)
// ---------------------------------------------------------------------------
extern "C" void kernel_launch(void* const* d_in, const int* in_sizes, int n_in,
                              void* d_out, int out_size)
{
    const float* query = (const float*)d_in[0];
    const float* key_  = (const float*)d_in[1];
    const float* value = (const float*)d_in[2];
    const float* W_q   = (const float*)d_in[3];
    const float* b_q   = (const float*)d_in[4];
    const float* W_k   = (const float*)d_in[5];
    const float* b_k   = (const float*)d_in[6];
    const float* W_v   = (const float*)d_in[7];
    const float* b_v   = (const float*)d_in[8];
    const float* W_o   = (const float*)d_in[9];
    const float* b_o   = (const float*)d_in[10];
    float* out = (float*)d_out;

    dim3 gg(64, 8);   // 8192/128 row tiles x 8 col tiles (heads / N-slices)

    // q/k/v projections: per-head weight blocks [512,64], ldb=64
    gemm512_kernel<<<gg, 128>>>(query, W_q, b_q, nullptr, 512 * 64, 64, 0, 1);
    gemm512_kernel<<<gg, 128>>>(key_,  W_k, b_k, nullptr, 512 * 64, 64, 0, 2);
    gemm512_kernel<<<gg, 128>>>(value, W_v, b_v, nullptr, 512 * 64, 64, 0, 3);

    // causal attention: 32 q-tiles x 32 (b,h) planes
    attn_kernel<<<dim3(32, 32), 256>>>();

    // output projection: concat [8192,512] @ W_o [512,512] + b_o
    gemm512_kernel<<<gg, 128>>>(nullptr, W_o, b_o, out, 64, 512, 1, 0);
}